// round 1
// baseline (speedup 1.0000x reference)
#include <cuda_runtime.h>

// Problem constants (fixed shapes)
#define T_  4
#define B_  64
#define N_  1024
#define P_  63
#define D_  128
#define M_  (T_*B_*N_)        // 262144 rows
#define TBND (B_*N_*D_)       // 8388608, t-stride in h/out
#define NBLK (M_/64)          // 4096 GEMM blocks

// Scratch (device globals: allocation-free per harness rules)
__device__ float g_h[(size_t)M_ * D_];       // 134 MB intermediate h
__device__ float g_wt[P_ * D_];              // W transposed [p][d]
__device__ float g_psum[NBLK * D_];          // per-block channel partial sums
__device__ float g_psq[NBLK * D_];           // per-block channel partial sumsq
__device__ float g_mean[D_];
__device__ float g_rstd[D_];

// ---- packed fp32x2 helpers (B300 2xFP32 pipe) ----
__device__ __forceinline__ unsigned long long pk2(float a){
    unsigned long long r;
    asm("mov.b64 %0, {%1, %1};" : "=l"(r) : "f"(a));
    return r;
}
__device__ __forceinline__ void fma2(unsigned long long& d,
                                     unsigned long long a, unsigned long long b){
    asm("fma.rn.f32x2 %0, %1, %2, %0;" : "+l"(d) : "l"(a), "l"(b));
}
__device__ __forceinline__ float2 up2(unsigned long long v){
    float2 f;
    asm("mov.b64 {%0, %1}, %2;" : "=f"(f.x), "=f"(f.y) : "l"(v));
    return f;
}

// ---- K0: transpose W [128][63] -> g_wt [63][128] (tiny) ----
__global__ void k_wt(const float* __restrict__ W){
    int idx = blockIdx.x * blockDim.x + threadIdx.x;
    if (idx < P_ * D_){
        int d = idx / P_;
        int p = idx - d * P_;
        g_wt[p * D_ + d] = W[idx];
    }
}

// ---- K1: GEMM h = x @ W^T + per-block channel stats ----
// Block tile: 64 rows x 128 cols (full D), K=63. 256 threads: 16x16,
// each thread computes 4 rows x 8 cols (4 f32x2 column-pairs).
__global__ __launch_bounds__(256) void k_gemm(const float* __restrict__ x){
    __shared__ __align__(16) float xs[64 * 64];   // x tile [r][p], stride 64 (16 KB)
    __shared__ __align__(16) float ws[P_ * D_];   // W^T tile [p][d]      (31.5 KB)

    const int blk = blockIdx.x;
    const int tid = threadIdx.x;

    // load x tile: 64*63 = 4032 contiguous floats, fully coalesced
    const float* xg = x + (size_t)blk * (64 * P_);
    #pragma unroll
    for (int k = 0; k < 16; k++){
        int idx = tid + k * 256;
        if (idx < 64 * P_){
            int r = idx / P_;
            int p = idx - r * P_;
            xs[r * 64 + p] = xg[idx];
        }
    }
    // load W^T: 8064 contiguous floats (conflict-free, coalesced)
    #pragma unroll
    for (int k = 0; k < 32; k++){
        int idx = tid + k * 256;
        if (idx < P_ * D_) ws[idx] = g_wt[idx];
    }
    __syncthreads();

    const int tx = tid & 15;
    const int ty = tid >> 4;

    unsigned long long acc[4][4];
    #pragma unroll
    for (int i = 0; i < 4; i++)
        #pragma unroll
        for (int j = 0; j < 4; j++)
            acc[i][j] = 0ull;

    const float* xr = xs + (ty * 4) * 64;
    const float* wc = ws + tx * 8;

    #pragma unroll 7
    for (int p = 0; p < P_; p++){
        unsigned long long a0 = pk2(xr[p]);
        unsigned long long a1 = pk2(xr[64 + p]);
        unsigned long long a2 = pk2(xr[128 + p]);
        unsigned long long a3 = pk2(xr[192 + p]);
        const ulonglong2* wp = (const ulonglong2*)(wc + p * D_);
        ulonglong2 b01 = wp[0];
        ulonglong2 b23 = wp[1];
        fma2(acc[0][0], a0, b01.x); fma2(acc[0][1], a0, b01.y);
        fma2(acc[0][2], a0, b23.x); fma2(acc[0][3], a0, b23.y);
        fma2(acc[1][0], a1, b01.x); fma2(acc[1][1], a1, b01.y);
        fma2(acc[1][2], a1, b23.x); fma2(acc[1][3], a1, b23.y);
        fma2(acc[2][0], a2, b01.x); fma2(acc[2][1], a2, b01.y);
        fma2(acc[2][2], a2, b23.x); fma2(acc[2][3], a2, b23.y);
        fma2(acc[3][0], a3, b01.x); fma2(acc[3][1], a3, b01.y);
        fma2(acc[3][2], a3, b23.x); fma2(acc[3][3], a3, b23.y);
    }

    // write h + accumulate local channel stats
    float cs[8], cq[8];
    #pragma unroll
    for (int c = 0; c < 8; c++){ cs[c] = 0.f; cq[c] = 0.f; }

    #pragma unroll
    for (int i = 0; i < 4; i++){
        size_t rowg = (size_t)blk * 64 + ty * 4 + i;
        ulonglong2* dst = (ulonglong2*)(g_h + rowg * D_ + tx * 8);
        ulonglong2 v0; v0.x = acc[i][0]; v0.y = acc[i][1];
        ulonglong2 v1; v1.x = acc[i][2]; v1.y = acc[i][3];
        dst[0] = v0;
        dst[1] = v1;
        #pragma unroll
        for (int j = 0; j < 4; j++){
            float2 f = up2(acc[i][j]);
            cs[2*j]   += f.x;  cq[2*j]   += f.x * f.x;
            cs[2*j+1] += f.y;  cq[2*j+1] += f.y * f.y;
        }
    }

    // block-level channel reduction (reuse xs: 4096 floats = 2x 16x128)
    __syncthreads();
    #pragma unroll
    for (int c = 0; c < 8; c++){
        xs[ty * 128 + tx * 8 + c]        = cs[c];
        xs[2048 + ty * 128 + tx * 8 + c] = cq[c];
    }
    __syncthreads();
    if (tid < 128){
        float s = 0.f, q = 0.f;
        #pragma unroll
        for (int r = 0; r < 16; r++){
            s += xs[r * 128 + tid];
            q += xs[2048 + r * 128 + tid];
        }
        g_psum[blk * D_ + tid] = s;
        g_psq [blk * D_ + tid] = q;
    }
}

// ---- K2: finalize per-channel mean / rstd (128 blocks, double accum) ----
__global__ __launch_bounds__(256) void k_stats(){
    __shared__ double ss[256];
    __shared__ double sq[256];
    const int d = blockIdx.x;
    const int t = threadIdx.x;
    double s = 0.0, q = 0.0;
    for (int b = t; b < NBLK; b += 256){
        s += (double)g_psum[b * D_ + d];
        q += (double)g_psq [b * D_ + d];
    }
    ss[t] = s; sq[t] = q;
    __syncthreads();
    for (int o = 128; o > 0; o >>= 1){
        if (t < o){ ss[t] += ss[t + o]; sq[t] += sq[t + o]; }
        __syncthreads();
    }
    if (t == 0){
        double mean = ss[0] / (double)M_;
        double ex2  = sq[0] / (double)M_;
        float meanf = (float)mean;
        float varf  = (float)(ex2 - mean * mean);   // biased var, torch-BN style
        float ve    = varf + 1e-5f;                 // eps added in fp32 like ref
        g_mean[d] = meanf;
        g_rstd[d] = (float)(1.0 / sqrt((double)ve));
    }
}

// ---- K3: normalize + 4-step LIF, vectorized float4 over D ----
__global__ __launch_bounds__(256) void k_lif(const float* __restrict__ gamma,
                                             const float* __restrict__ beta,
                                             float* __restrict__ out){
    int i = blockIdx.x * 256 + threadIdx.x;       // 0 .. 2097151
    int d0 = (i << 2) & 127;
    float4 mn = *(const float4*)(g_mean + d0);
    float4 rs = *(const float4*)(g_rstd + d0);
    float4 gm = *(const float4*)(gamma + d0);
    float4 bt = *(const float4*)(beta  + d0);
    size_t base = (size_t)i << 2;

    float v0 = 0.f, v1 = 0.f, v2 = 0.f, v3 = 0.f;
    #pragma unroll
    for (int t = 0; t < 4; t++){
        float4 h = *(const float4*)(g_h + base + (size_t)t * TBND);
        float n0 = (h.x - mn.x) * rs.x * gm.x + bt.x;
        float n1 = (h.y - mn.y) * rs.y * gm.y + bt.y;
        float n2 = (h.z - mn.z) * rs.z * gm.z + bt.z;
        float n3 = (h.w - mn.w) * rs.w * gm.w + bt.w;
        // v = v + (x - v)/tau, tau=2 -> (x-v)*0.5f is exact
        v0 = v0 + (n0 - v0) * 0.5f;
        v1 = v1 + (n1 - v1) * 0.5f;
        v2 = v2 + (n2 - v2) * 0.5f;
        v3 = v3 + (n3 - v3) * 0.5f;
        float4 o;
        o.x = (v0 >= 1.0f) ? 1.0f : 0.0f;
        o.y = (v1 >= 1.0f) ? 1.0f : 0.0f;
        o.z = (v2 >= 1.0f) ? 1.0f : 0.0f;
        o.w = (v3 >= 1.0f) ? 1.0f : 0.0f;
        if (v0 >= 1.0f) v0 = 0.f;     // hard reset
        if (v1 >= 1.0f) v1 = 0.f;
        if (v2 >= 1.0f) v2 = 0.f;
        if (v3 >= 1.0f) v3 = 0.f;
        *(float4*)(out + base + (size_t)t * TBND) = o;
    }
}

extern "C" void kernel_launch(void* const* d_in, const int* in_sizes, int n_in,
                              void* d_out, int out_size){
    const float* x     = (const float*)d_in[0];   // [4,64,1024,63]
    const float* W     = (const float*)d_in[1];   // [128,63]
    const float* gamma = (const float*)d_in[2];   // [128]
    const float* beta  = (const float*)d_in[3];   // [128]
    // d_in[4] = pe (unused, pe=0 branch)
    float* out = (float*)d_out;                   // [4,64,1024,128] fp32

    k_wt   <<<32, 256>>>(W);
    k_gemm <<<NBLK, 256>>>(x);
    k_stats<<<D_, 256>>>();
    k_lif  <<<TBND / 4 / 256, 256>>>(gamma, beta, out);
}

// round 3
// speedup vs baseline: 1.4246x; 1.4246x over previous
#include <cuda_runtime.h>
#include <cuda_bf16.h>
#include <cstdint>

// ---------------- problem constants ----------------
#define T_    4
#define NBN   65536
#define P_    63
#define D_    128
#define M_    262144
#define TBND  8388608
#define NBLK  2048              // GEMM blocks (128 rows each)

// dynamic smem: A limbs [0,49152), B limbs [49152,98304). Stage reuses [0,67584).
#define SM_GEMM 98304

// ---------------- device globals ----------------
__device__ float g_h[(size_t)M_ * D_];                 // 134 MB intermediate
__device__ __align__(16) unsigned char g_wb[49152];    // 3 pre-swizzled W bf16 limb tiles
__device__ float g_psum[NBLK * D_];
__device__ float g_psq [NBLK * D_];
__device__ float g_mean[D_];
__device__ float g_rstd[D_];

// ---------------- helpers ----------------
__device__ __forceinline__ uint32_t smem_u32(const void* p){
    uint32_t a;
    asm("{ .reg .u64 t; cvta.to.shared.u64 t, %1; cvt.u32.u64 %0, t; }" : "=r"(a) : "l"(p));
    return a;
}
__device__ __forceinline__ void ldsm4(uint32_t* r, uint32_t addr){
    asm volatile("ldmatrix.sync.aligned.m8n8.x4.shared.b16 {%0,%1,%2,%3}, [%4];"
        : "=r"(r[0]), "=r"(r[1]), "=r"(r[2]), "=r"(r[3]) : "r"(addr));
}
__device__ __forceinline__ void mma16816(float* c, const uint32_t* a, const uint32_t* b){
    asm volatile("mma.sync.aligned.m16n8k16.row.col.f32.bf16.bf16.f32 "
        "{%0,%1,%2,%3}, {%4,%5,%6,%7}, {%8,%9}, {%0,%1,%2,%3};"
        : "+f"(c[0]), "+f"(c[1]), "+f"(c[2]), "+f"(c[3])
        : "r"(a[0]), "r"(a[1]), "r"(a[2]), "r"(a[3]), "r"(b[0]), "r"(b[1]));
}

// swizzled offset inside a [128 rows x 64 bf16] tile (128B rows, 16B chunks XOR row)
__device__ __forceinline__ uint32_t sw_off(int row, int k){
    return (uint32_t)(row * 128 + ((((k >> 3) ^ row) & 7) << 4) + ((k & 7) << 1));
}

// ---------------- K0: W -> 3 pre-swizzled bf16 limb tiles ----------------
__global__ __launch_bounds__(256) void k_wt(const float* __restrict__ W){
    int idx = blockIdx.x * 256 + threadIdx.x;     // 0..8191
    if (idx >= D_ * 64) return;
    int d = idx >> 6;
    int k = idx & 63;
    float w = (k < P_) ? W[d * P_ + k] : 0.f;
    __nv_bfloat16 w0 = __float2bfloat16(w);
    float r1 = w - __bfloat162float(w0);
    __nv_bfloat16 w1 = __float2bfloat16(r1);
    float r2 = r1 - __bfloat162float(w1);
    __nv_bfloat16 w2 = __float2bfloat16(r2);
    uint32_t off = sw_off(d, k);
    *(__nv_bfloat16*)(g_wb + off)         = w0;
    *(__nv_bfloat16*)(g_wb + 16384 + off) = w1;
    *(__nv_bfloat16*)(g_wb + 32768 + off) = w2;
}

// ---------------- K1: split-bf16 HMMA GEMM + h write + channel stats ----------------
__global__ __launch_bounds__(256, 2) void k_gemm(const float* __restrict__ x){
    extern __shared__ __align__(1024) unsigned char smem[];
    const uint32_t sb = smem_u32(smem);
    const int tid = threadIdx.x;
    const int w   = tid >> 5;
    const int l   = tid & 31;
    const int blk = blockIdx.x;

    // B limbs: straight 48KB copy of pre-swizzled tiles
    {
        uint4* bs = (uint4*)(smem + 49152);
        const uint4* gs = (const uint4*)g_wb;
        #pragma unroll
        for (int i = 0; i < 12; i++) bs[tid + i * 256] = gs[tid + i * 256];
    }
    // A limbs: load x tile (128 rows x 63, contiguous), split into 3 bf16 limbs
    {
        const float* xg = x + (size_t)blk * (128 * P_);
        for (int i = tid; i < 128 * P_; i += 256){
            int r = i / P_;
            int k = i - r * P_;
            float v = xg[i];
            __nv_bfloat16 h0 = __float2bfloat16(v);
            float r1 = v - __bfloat162float(h0);
            __nv_bfloat16 h1 = __float2bfloat16(r1);
            float r2 = r1 - __bfloat162float(h1);
            __nv_bfloat16 h2 = __float2bfloat16(r2);
            uint32_t off = sw_off(r, k);
            *(__nv_bfloat16*)(smem + off)         = h0;
            *(__nv_bfloat16*)(smem + 16384 + off) = h1;
            *(__nv_bfloat16*)(smem + 32768 + off) = h2;
        }
        if (tid < 128){            // zero-pad k=63
            uint32_t off = sw_off(tid, 63);
            *(__nv_bfloat16*)(smem + off)         = __nv_bfloat16(0.f);
            *(__nv_bfloat16*)(smem + 16384 + off) = __nv_bfloat16(0.f);
            *(__nv_bfloat16*)(smem + 32768 + off) = __nv_bfloat16(0.f);
        }
    }
    __syncthreads();

    // lane constants
    const int g     = l >> 3;                       // ldmatrix group 0..3
    const int a_row = w * 16 + (l & 7) + (g & 1) * 8;
    const int a_r7  = a_row & 7;
    const int a_kb  = g >> 1;                       // k-chunk bit for A
    const uint32_t aRowBase = sb + (uint32_t)a_row * 128;

    const int b_rl  = (l & 7) + ((l >> 4) & 1) * 8; // row within 16-row tile pair
    const int b_r7  = b_rl & 7;
    const int b_kb  = (l >> 3) & 1;                 // k-chunk bit for B

    float acc[16][4];
    #pragma unroll
    for (int t = 0; t < 16; t++)
        #pragma unroll
        for (int e = 0; e < 4; e++) acc[t][e] = 0.f;

    // products (ai,bi): bi=0 -> ai {0,1,2}; bi=1 -> {0,1}; bi=2 -> {0}
    #pragma unroll
    for (int ks = 0; ks < 4; ks++){
        #pragma unroll
        for (int grp = 0; grp < 2; grp++){
            #pragma unroll
            for (int bi = 0; bi < 3; bi++){
                uint32_t bfr[4][4];
                #pragma unroll
                for (int j = 0; j < 4; j++){
                    int row = grp * 64 + j * 16 + b_rl;
                    uint32_t addr = sb + 49152 + bi * 16384 + (uint32_t)row * 128
                                  + (uint32_t)((((ks * 2 + b_kb) ^ b_r7) & 7) << 4);
                    ldsm4(bfr[j], addr);
                }
                #pragma unroll
                for (int a = 0; a < 3 - bi; a++){
                    uint32_t af[4];
                    uint32_t addrA = aRowBase + a * 16384
                                   + (uint32_t)((((ks * 2 + a_kb) ^ a_r7) & 7) << 4);
                    ldsm4(af, addrA);
                    #pragma unroll
                    for (int j = 0; j < 4; j++){
                        mma16816(acc[grp * 8 + 2 * j],     af, &bfr[j][0]);
                        mma16816(acc[grp * 8 + 2 * j + 1], af, &bfr[j][2]);
                    }
                }
            }
        }
    }

    // ---- epilogue: stage, coalesced h write, channel stats ----
    __syncthreads();                       // all operand reads done
    float* stg = (float*)smem;             // [128][132]
    const int r0 = w * 16 + (l >> 2);
    const int cq = (l & 3) * 2;
    #pragma unroll
    for (int t = 0; t < 16; t++){
        *(float2*)(stg + r0 * 132 + t * 8 + cq)       = make_float2(acc[t][0], acc[t][1]);
        *(float2*)(stg + (r0 + 8) * 132 + t * 8 + cq) = make_float2(acc[t][2], acc[t][3]);
    }
    __syncthreads();

    float* hg = g_h + (size_t)blk * (128 * 128);
    #pragma unroll
    for (int j = 0; j < 16; j++){
        int idx = tid + j * 256;
        int row = idx >> 5;
        int c4  = idx & 31;
        float4 v = *(const float4*)(stg + row * 132 + c4 * 4);
        *(float4*)(hg + row * 128 + c4 * 4) = v;
    }

    if (tid < 128){
        float s = 0.f;
        #pragma unroll 8
        for (int r = 0; r < 128; r++) s += stg[r * 132 + tid];
        g_psum[blk * D_ + tid] = s;
    } else {
        int d = tid - 128;
        float q = 0.f;
        #pragma unroll 8
        for (int r = 0; r < 128; r++){ float v = stg[r * 132 + d]; q += v * v; }
        g_psq[blk * D_ + d] = q;
    }
}

// ---------------- K2: finalize stats (double), fold gamma/beta ----------------
__global__ __launch_bounds__(256) void k_stats(const float* __restrict__ gamma,
                                               const float* __restrict__ beta){
    __shared__ double ss[256];
    __shared__ double sq[256];
    const int d = blockIdx.x;
    const int t = threadIdx.x;
    double s = 0.0, q = 0.0;
    for (int b = t; b < NBLK; b += 256){
        s += (double)g_psum[b * D_ + d];
        q += (double)g_psq [b * D_ + d];
    }
    ss[t] = s; sq[t] = q;
    __syncthreads();
    for (int o = 128; o > 0; o >>= 1){
        if (t < o){ ss[t] += ss[t + o]; sq[t] += sq[t + o]; }
        __syncthreads();
    }
    if (t == 0){
        double mean = ss[0] / (double)M_;
        double ex2  = sq[0] / (double)M_;
        float meanf = (float)mean;
        float varf  = (float)(ex2 - mean * mean);
        float rstd  = (float)(1.0 / sqrt((double)(varf + 1e-5f)));
        float gm = gamma[d], bt = beta[d];
        float rs = rstd * gm;
        float mn = (rs != 0.f) ? (meanf - bt / rs) : meanf;
        g_mean[d] = mn;
        g_rstd[d] = rs;
    }
}

// ---------------- K3: BN + 4-step LIF, float4 over D ----------------
__global__ __launch_bounds__(256) void k_lif(float* __restrict__ out){
    int i = blockIdx.x * 256 + threadIdx.x;
    int d0 = (i << 2) & 127;
    float4 mn = *(const float4*)(g_mean + d0);
    float4 rs = *(const float4*)(g_rstd + d0);
    size_t base = (size_t)i << 2;

    float v0 = 0.f, v1 = 0.f, v2 = 0.f, v3 = 0.f;
    #pragma unroll
    for (int t = 0; t < 4; t++){
        float4 h = *(const float4*)(g_h + base + (size_t)t * TBND);
        float n0 = (h.x - mn.x) * rs.x;
        float n1 = (h.y - mn.y) * rs.y;
        float n2 = (h.z - mn.z) * rs.z;
        float n3 = (h.w - mn.w) * rs.w;
        v0 = v0 + (n0 - v0) * 0.5f;
        v1 = v1 + (n1 - v1) * 0.5f;
        v2 = v2 + (n2 - v2) * 0.5f;
        v3 = v3 + (n3 - v3) * 0.5f;
        float4 o;
        o.x = (v0 >= 1.0f) ? 1.0f : 0.0f;
        o.y = (v1 >= 1.0f) ? 1.0f : 0.0f;
        o.z = (v2 >= 1.0f) ? 1.0f : 0.0f;
        o.w = (v3 >= 1.0f) ? 1.0f : 0.0f;
        if (v0 >= 1.0f) v0 = 0.f;
        if (v1 >= 1.0f) v1 = 0.f;
        if (v2 >= 1.0f) v2 = 0.f;
        if (v3 >= 1.0f) v3 = 0.f;
        *(float4*)(out + base + (size_t)t * TBND) = o;
    }
}

// ---------------- launch ----------------
extern "C" void kernel_launch(void* const* d_in, const int* in_sizes, int n_in,
                              void* d_out, int out_size){
    const float* x     = (const float*)d_in[0];
    const float* W     = (const float*)d_in[1];
    const float* gamma = (const float*)d_in[2];
    const float* beta  = (const float*)d_in[3];
    float* out = (float*)d_out;

    cudaFuncSetAttribute(k_gemm, cudaFuncAttributeMaxDynamicSharedMemorySize, SM_GEMM);

    k_wt   <<<32, 256>>>(W);
    k_gemm <<<NBLK, 256, SM_GEMM>>>(x);
    k_stats<<<D_, 256>>>(gamma, beta);
    k_lif  <<<TBND / 4 / 256, 256>>>(out);
}